// round 6
// baseline (speedup 1.0000x reference)
#include <cuda_runtime.h>
#include <cuda_fp16.h>
#include <cstdint>

// ---------------------------------------------------------------------------
// Problem constants
// ---------------------------------------------------------------------------
#define N_ROWS 100000
#define HID    512
#define D_IN   64
#define PH     16
#define NOBS   50000
#define K1     1024      // PH*D
#define K2     512       // HID
#define H3     1536      // 3*HID
#define MTILES ((NOBS + 127) / 128)   // 391

// ---------------------------------------------------------------------------
// Scratch (__device__ globals — sanctioned scratch path, no runtime allocs)
// ---------------------------------------------------------------------------
__device__ __half g_Wih_h[(size_t)H3 * K1];     //  3 MB
__device__ __half g_Whh_h[(size_t)H3 * K2];     //  1.5 MB
__device__ __half g_gruin[(size_t)NOBS * K1];   // 100 MB
__device__ __half g_hgat [(size_t)NOBS * K2];   //  50 MB
__device__ __half g_gi   [(size_t)NOBS * H3];   // 150 MB
__device__ __half g_gh   [(size_t)NOBS * H3];   // 150 MB
__device__ float  g_loss;

// ---------------------------------------------------------------------------
// Helpers
// ---------------------------------------------------------------------------
__device__ __forceinline__ uint32_t smem_to_u32(const void* smem_ptr) {
    uint32_t addr;
    asm("{ .reg .u64 tmp; cvta.to.shared.u64 tmp, %1; cvt.u32.u64 %0, tmp; }"
        : "=r"(addr) : "l"(smem_ptr));
    return addr;
}

__device__ __forceinline__ void cp_async16(uint32_t dst, const void* src, int src_bytes) {
    asm volatile("cp.async.cg.shared.global [%0], [%1], 16, %2;"
                 :: "r"(dst), "l"(src), "r"(src_bytes));
}
#define CP_ASYNC_COMMIT() asm volatile("cp.async.commit_group;" ::: "memory")
#define CP_ASYNC_WAIT_2() asm volatile("cp.async.wait_group 2;" ::: "memory")

#define LDMATRIX_X4(r0, r1, r2, r3, addr) \
    asm volatile("ldmatrix.sync.aligned.m8n8.x4.shared.b16 {%0,%1,%2,%3}, [%4];" \
                 : "=r"(r0), "=r"(r1), "=r"(r2), "=r"(r3) : "r"(addr))

// fp16-accumulator HMMA: D(fp16x2 pair) = A*B + D
#define MMA_16816_F16(c, a0, a1, a2, a3, b0, b1) \
    asm volatile("mma.sync.aligned.m16n8k16.row.col.f16.f16.f16.f16 " \
                 "{%0,%1}, {%2,%3,%4,%5}, {%6,%7}, {%0,%1};" \
                 : "+r"((c)[0]), "+r"((c)[1]) \
                 : "r"(a0), "r"(a1), "r"(a2), "r"(a3), "r"(b0), "r"(b1))

// ---------------------------------------------------------------------------
// 1. Weight convert + loss zero
// ---------------------------------------------------------------------------
__global__ void convert_weights_kernel(const float* __restrict__ wih,
                                       const float* __restrict__ whh) {
    const int n1 = H3 * K1;
    const int n2 = H3 * K2;
    for (int i = blockIdx.x * blockDim.x + threadIdx.x; i < n1 + n2;
         i += gridDim.x * blockDim.x) {
        if (i < n1) g_Wih_h[i] = __float2half_rn(wih[i]);
        else        g_Whh_h[i - n1] = __float2half_rn(whh[i - n1]);
    }
    if (blockIdx.x == 0 && threadIdx.x == 0) g_loss = 0.0f;
}

// ---------------------------------------------------------------------------
// 2. Prep: loss + feats einsum + relu*mask -> g_gruin (fp16)
// ---------------------------------------------------------------------------
__global__ void __launch_bounds__(256) prep_kernel(
    const float* __restrict__ p, const float* __restrict__ X,
    const float* __restrict__ M, const int* __restrict__ iobs,
    const float* __restrict__ wprep, const float* __restrict__ bprep) {
    __shared__ float sw[D_IN * 64];   // [d][f*16+j]
    __shared__ float sb[D_IN * PH];
    __shared__ float sred[256];

    for (int i = threadIdx.x; i < D_IN * 64; i += 256) sw[i] = wprep[i];
    for (int i = threadIdx.x; i < D_IN * PH; i += 256) sb[i] = bprep[i];
    __syncthreads();

    const int d   = threadIdx.x & 63;
    const int sub = threadIdx.x >> 6;   // 0..3
    const int base = blockIdx.x * 32;
    float lacc = 0.0f;

    for (int rr = sub; rr < 32; rr += 4) {
        const int r = base + rr;
        if (r >= NOBS) continue;
        const int i = iobs[r];
        const float mean = p[(size_t)i * 128 + d];
        const float var  = fabsf(p[(size_t)i * 128 + 64 + d]) + 1e-6f;
        const float x    = X[(size_t)r * 64 + d];
        const float m    = M[(size_t)r * 64 + d];
        const float rsv  = rsqrtf(var);
        const float err  = (x - mean) * rsv;
        lacc += 0.5f * (err * err + logf(var)) * m;

        const float* w = sw + d * 64;
        const float* b = sb + d * 16;
        __half2 hv[8];
        #pragma unroll
        for (int j = 0; j < 16; j += 2) {
            float v0 = b[j];
            v0 = fmaf(x, w[j], v0);
            v0 = fmaf(mean, w[16 + j], v0);
            v0 = fmaf(var,  w[32 + j], v0);
            v0 = fmaf(err,  w[48 + j], v0);
            float v1 = b[j + 1];
            v1 = fmaf(x, w[j + 1], v1);
            v1 = fmaf(mean, w[16 + j + 1], v1);
            v1 = fmaf(var,  w[32 + j + 1], v1);
            v1 = fmaf(err,  w[48 + j + 1], v1);
            v0 = fmaxf(v0, 0.0f) * m;
            v1 = fmaxf(v1, 0.0f) * m;
            hv[j >> 1] = __floats2half2_rn(v0, v1);
        }
        uint4* dst = reinterpret_cast<uint4*>(&g_gruin[(size_t)r * K1 + d * 16]);
        dst[0] = *reinterpret_cast<uint4*>(&hv[0]);
        dst[1] = *reinterpret_cast<uint4*>(&hv[4]);
    }

    sred[threadIdx.x] = lacc;
    __syncthreads();
    for (int s = 128; s > 0; s >>= 1) {
        if (threadIdx.x < s) sred[threadIdx.x] += sred[threadIdx.x + s];
        __syncthreads();
    }
    if (threadIdx.x == 0) atomicAdd(&g_loss, sred[0]);
}

// ---------------------------------------------------------------------------
// 3. Gather h[i_obs] -> fp16
// ---------------------------------------------------------------------------
__global__ void gather_h_kernel(const float* __restrict__ h,
                                const int* __restrict__ iobs) {
    const int total = NOBS * (HID / 2);
    int idx = blockIdx.x * blockDim.x + threadIdx.x;
    if (idx >= total) return;
    const int r = idx >> 8;          // HID/2 = 256
    const int c = idx & 255;
    const int i = iobs[r];
    float2 v = *reinterpret_cast<const float2*>(&h[(size_t)i * HID + c * 2]);
    reinterpret_cast<__half2*>(g_hgat)[idx] = __floats2half2_rn(v.x, v.y);
}

// ---------------------------------------------------------------------------
// 4. HMMA GEMM: C[M,1536](fp16) = A[M,K](fp16) @ B[1536,K](fp16)^T
//    BM=128, BN=128, BK=32, 4-stage cp.async multistage, 256 thr
//    (8 warps, 4m x 2n), warp tile 32x64, mma.sync m16n8k16 with FP16
//    accumulators (full tensor rate), flushed into fp32 masters every
//    KSPLIT=64 of K (2 chunks) to bound fp16 accumulation error.
// ---------------------------------------------------------------------------
#define STAGES       4
#define STAGE_BYTES  20480          // A 10240 + B 10240
#define SM_B_OFF     10240

__device__ __forceinline__ void load_stage(uint32_t sm, int stage,
                                           const __half* __restrict__ A,
                                           const __half* __restrict__ B,
                                           int m0, int n0, int K, int kc, int tid) {
    const uint32_t base = sm + stage * STAGE_BYTES;
    #pragma unroll
    for (int it = 0; it < 4; it++) {
        const int c = tid + it * 256;           // 0..1023
        const int cc = c & 511;
        const int row = cc >> 2, ch = cc & 3;   // 128 rows x 4 x 16B
        if (c < 512) {  // A
            const int rg = m0 + row;
            const int rc = rg < NOBS ? rg : (NOBS - 1);
            const void* src = A + (size_t)rc * K + kc * 32 + ch * 8;
            cp_async16(base + row * 80 + ch * 16, src, rg < NOBS ? 16 : 0);
        } else {        // B (always in range)
            const void* src = B + (size_t)(n0 + row) * K + kc * 32 + ch * 8;
            cp_async16(base + SM_B_OFF + row * 80 + ch * 16, src, 16);
        }
    }
}

__global__ void __launch_bounds__(256, 2) gemm_hmma_kernel(
    const __half* __restrict__ A, const __half* __restrict__ B,
    __half* __restrict__ C, int K) {
    extern __shared__ __align__(128) char smem[];   // STAGES * STAGE_BYTES
    const uint32_t sm = smem_to_u32(smem);

    const int tid  = threadIdx.x;
    const int lane = tid & 31;
    const int wid  = tid >> 5;
    const int warp_m = wid & 3;     // 4 m-warps, 32 rows each
    const int warp_n = wid >> 2;    // 2 n-warps, 64 cols each

    const int n0 = blockIdx.x * 128;
    const int m0 = blockIdx.y * 128;
    const int nk = K >> 5;

    // per-lane ldmatrix base offsets (bytes) within a stage
    const uint32_t lrow = lane & 15;
    const uint32_t lcol = (lane >> 4) << 4;   // 0 or 16 bytes (8 halfs)
    const uint32_t a_off = (warp_m * 32 + lrow) * 80 + lcol;
    const uint32_t b_off = SM_B_OFF + (warp_n * 64 + lrow) * 80 + lcol;

    float acc[2][8][4];           // fp32 master accumulators
    uint32_t hacc[2][8][2];       // fp16x2 working accumulators
    #pragma unroll
    for (int mt = 0; mt < 2; mt++)
        #pragma unroll
        for (int nt = 0; nt < 8; nt++) {
            #pragma unroll
            for (int e = 0; e < 4; e++) acc[mt][nt][e] = 0.0f;
            hacc[mt][nt][0] = 0u; hacc[mt][nt][1] = 0u;
        }

    // prologue: stages 0..2
    #pragma unroll
    for (int s = 0; s < 3; s++) {
        load_stage(sm, s, A, B, m0, n0, K, s, tid);
        CP_ASYNC_COMMIT();
    }

    for (int kc = 0; kc < nk; kc++) {
        const int buf = kc & 3;
        CP_ASYNC_WAIT_2();          // chunk kc landed (<=2 newer in flight)
        __syncthreads();            // all warps past iteration kc-1's reads

        // prefetch chunk kc+3 into buffer (kc+3)&3 == (kc-1)&3 (just freed)
        if (kc + 3 < nk) load_stage(sm, (kc + 3) & 3, A, B, m0, n0, K, kc + 3, tid);
        CP_ASYNC_COMMIT();          // (possibly empty) group keeps counts exact

        const uint32_t sA = sm + buf * STAGE_BYTES;   // b_off includes SM_B_OFF

        #pragma unroll
        for (int ks = 0; ks < 2; ks++) {
            const uint32_t k0b = ks * 32;      // 16 halfs = 32 bytes
            uint32_t a[2][4];
            LDMATRIX_X4(a[0][0], a[0][1], a[0][2], a[0][3], sA + a_off + k0b);
            LDMATRIX_X4(a[1][0], a[1][1], a[1][2], a[1][3], sA + a_off + 1280 + k0b);
            uint32_t b[8][2];
            #pragma unroll
            for (int nb = 0; nb < 4; nb++) {
                uint32_t r0, r1, r2, r3;
                LDMATRIX_X4(r0, r1, r2, r3, sA + b_off + nb * 1280 + k0b);
                b[2 * nb][0] = r0; b[2 * nb][1] = r2;
                b[2 * nb + 1][0] = r1; b[2 * nb + 1][1] = r3;
            }
            #pragma unroll
            for (int mt = 0; mt < 2; mt++)
                #pragma unroll
                for (int nt = 0; nt < 8; nt++)
                    MMA_16816_F16(hacc[mt][nt],
                                  a[mt][0], a[mt][1], a[mt][2], a[mt][3],
                                  b[nt][0], b[nt][1]);
        }

        // flush fp16 partials into fp32 masters every 2 chunks (KSPLIT=64)
        if ((kc & 1) == 1 || kc == nk - 1) {
            #pragma unroll
            for (int mt = 0; mt < 2; mt++)
                #pragma unroll
                for (int nt = 0; nt < 8; nt++) {
                    const float2 lo = __half22float2(
                        *reinterpret_cast<__half2*>(&hacc[mt][nt][0]));
                    const float2 hi = __half22float2(
                        *reinterpret_cast<__half2*>(&hacc[mt][nt][1]));
                    acc[mt][nt][0] += lo.x;
                    acc[mt][nt][1] += lo.y;
                    acc[mt][nt][2] += hi.x;
                    acc[mt][nt][3] += hi.y;
                    hacc[mt][nt][0] = 0u;
                    hacc[mt][nt][1] = 0u;
                }
        }
        // no trailing sync: next iteration's wait+sync provides the barrier
    }

    // epilogue: fp32 -> fp16, store
    #pragma unroll
    for (int mt = 0; mt < 2; mt++) {
        const int r0 = m0 + warp_m * 32 + mt * 16 + (lane >> 2);
        #pragma unroll
        for (int nt = 0; nt < 8; nt++) {
            const int col = n0 + warp_n * 64 + nt * 8 + (lane & 3) * 2;
            if (r0 < NOBS)
                *reinterpret_cast<__half2*>(&C[(size_t)r0 * H3 + col]) =
                    __floats2half2_rn(acc[mt][nt][0], acc[mt][nt][1]);
            if (r0 + 8 < NOBS)
                *reinterpret_cast<__half2*>(&C[(size_t)(r0 + 8) * H3 + col]) =
                    __floats2half2_rn(acc[mt][nt][2], acc[mt][nt][3]);
        }
    }
}

// ---------------------------------------------------------------------------
// 5. Gate combine + scatter (last occurrence of each index wins)
// ---------------------------------------------------------------------------
__global__ void __launch_bounds__(128) combine_kernel(
    const int* __restrict__ iobs, const float* __restrict__ h,
    const float* __restrict__ bih, const float* __restrict__ bhh,
    float* __restrict__ out) {
    const int r = blockIdx.x;
    const int i = iobs[r];
    if (r + 1 < NOBS && iobs[r + 1] == i) return;   // not last occurrence

    const __half2* gi = reinterpret_cast<const __half2*>(&g_gi[(size_t)r * H3]);
    const __half2* gh = reinterpret_cast<const __half2*>(&g_gh[(size_t)r * H3]);
    const float2* b_ih = reinterpret_cast<const float2*>(bih);
    const float2* b_hh = reinterpret_cast<const float2*>(bhh);
    const float2* hrow = reinterpret_cast<const float2*>(&h[(size_t)i * HID]);
    float2* orow = reinterpret_cast<float2*>(&out[(size_t)i * HID]);

    for (int j = threadIdx.x; j < HID / 2; j += 128) {
        const float2 gir = __half22float2(gi[j]);
        const float2 giz = __half22float2(gi[256 + j]);
        const float2 gin = __half22float2(gi[512 + j]);
        const float2 ghr = __half22float2(gh[j]);
        const float2 ghz = __half22float2(gh[256 + j]);
        const float2 ghn = __half22float2(gh[512 + j]);
        const float2 bir = b_ih[j],       bhr = b_hh[j];
        const float2 biz = b_ih[256 + j], bhz = b_hh[256 + j];
        const float2 bin = b_ih[512 + j], bhn = b_hh[512 + j];
        const float2 hp = hrow[j];

        const float rg0 = 1.0f / (1.0f + expf(-(gir.x + bir.x + ghr.x + bhr.x)));
        const float rg1 = 1.0f / (1.0f + expf(-(gir.y + bir.y + ghr.y + bhr.y)));
        const float zg0 = 1.0f / (1.0f + expf(-(giz.x + biz.x + ghz.x + bhz.x)));
        const float zg1 = 1.0f / (1.0f + expf(-(giz.y + biz.y + ghz.y + bhz.y)));
        const float nn0 = tanhf(gin.x + bin.x + rg0 * (ghn.x + bhn.x));
        const float nn1 = tanhf(gin.y + bin.y + rg1 * (ghn.y + bhn.y));
        float2 o;
        o.x = (1.0f - zg0) * nn0 + zg0 * hp.x;
        o.y = (1.0f - zg1) * nn1 + zg1 * hp.y;
        orow[j] = o;
    }
}

// ---------------------------------------------------------------------------
// 6. Loss store
// ---------------------------------------------------------------------------
__global__ void write_loss_kernel(float* __restrict__ out) {
    out[(size_t)N_ROWS * HID] = g_loss;
}

// ---------------------------------------------------------------------------
// Launch
// ---------------------------------------------------------------------------
extern "C" void kernel_launch(void* const* d_in, const int* in_sizes, int n_in,
                              void* d_out, int out_size) {
    const float* h     = (const float*)d_in[0];
    const float* p     = (const float*)d_in[1];
    const float* X     = (const float*)d_in[2];
    const float* M     = (const float*)d_in[3];
    const int*   iobs  = (const int*)  d_in[4];
    const float* wprep = (const float*)d_in[5];
    const float* bprep = (const float*)d_in[6];
    const float* wih   = (const float*)d_in[7];
    const float* whh   = (const float*)d_in[8];
    const float* bih   = (const float*)d_in[9];
    const float* bhh   = (const float*)d_in[10];
    float* out = (float*)d_out;

    cudaFuncSetAttribute(gemm_hmma_kernel,
                         cudaFuncAttributeMaxDynamicSharedMemorySize,
                         STAGES * STAGE_BYTES);

    // 1. convert weights to fp16, zero loss accumulator
    convert_weights_kernel<<<512, 256>>>(wih, whh);

    // 2. out[:N*HID] = h
    cudaMemcpyAsync(out, h, (size_t)N_ROWS * HID * sizeof(float),
                    cudaMemcpyDeviceToDevice);

    // 3. prep: loss + gru_in (fp16)
    prep_kernel<<<(NOBS + 31) / 32, 256>>>(p, X, M, iobs, wprep, bprep);

    // 4. gather h[i_obs] -> fp16
    gather_h_kernel<<<(NOBS * (HID / 2) + 255) / 256, 256>>>(h, iobs);

    // device pointers to the scratch symbols for GEMM args
    __half *d_gruin, *d_hgat, *d_gi, *d_gh, *d_wih, *d_whh;
    cudaGetSymbolAddress((void**)&d_gruin, g_gruin);
    cudaGetSymbolAddress((void**)&d_hgat,  g_hgat);
    cudaGetSymbolAddress((void**)&d_gi,    g_gi);
    cudaGetSymbolAddress((void**)&d_gh,    g_gh);
    cudaGetSymbolAddress((void**)&d_wih,   g_Wih_h);
    cudaGetSymbolAddress((void**)&d_whh,   g_Whh_h);

    // 5. gi = gru_in @ Wih^T   (M=50000, N=1536, K=1024)
    gemm_hmma_kernel<<<dim3(12, MTILES), 256, STAGES * STAGE_BYTES>>>(
        d_gruin, d_wih, d_gi, K1);

    // 6. gh = h_gat @ Whh^T    (M=50000, N=1536, K=512)
    gemm_hmma_kernel<<<dim3(12, MTILES), 256, STAGES * STAGE_BYTES>>>(
        d_hgat, d_whh, d_gh, K2);

    // 7. gates + scatter (last-wins)
    combine_kernel<<<NOBS, 128>>>(iobs, h, bih, bhh, out);

    // 8. loss
    if (out_size > N_ROWS * HID)
        write_loss_kernel<<<1, 1>>>(out);
}

// round 7
// speedup vs baseline: 1.1169x; 1.1169x over previous
#include <cuda_runtime.h>
#include <cuda_fp16.h>
#include <cstdint>

// ---------------------------------------------------------------------------
// Problem constants
// ---------------------------------------------------------------------------
#define N_ROWS 100000
#define HID    512
#define D_IN   64
#define PH     16
#define NOBS   50000
#define K1     1024      // PH*D
#define K2     512       // HID
#define H3     1536      // 3*HID
#define MTILES ((NOBS + 127) / 128)   // 391

// ---------------------------------------------------------------------------
// Scratch (__device__ globals — sanctioned scratch path, no runtime allocs)
// ---------------------------------------------------------------------------
__device__ __half g_Wih_h[(size_t)H3 * K1];     //  3 MB
__device__ __half g_Whh_h[(size_t)H3 * K2];     //  1.5 MB
__device__ __half g_gruin[(size_t)NOBS * K1];   // 100 MB
__device__ __half g_hgat [(size_t)NOBS * K2];   //  50 MB
__device__ __half g_gi   [(size_t)NOBS * H3];   // 150 MB
__device__ __half g_gh   [(size_t)NOBS * H3];   // 150 MB
__device__ float  g_loss;

// ---------------------------------------------------------------------------
// Helpers
// ---------------------------------------------------------------------------
__device__ __forceinline__ uint32_t smem_to_u32(const void* smem_ptr) {
    uint32_t addr;
    asm("{ .reg .u64 tmp; cvta.to.shared.u64 tmp, %1; cvt.u32.u64 %0, tmp; }"
        : "=r"(addr) : "l"(smem_ptr));
    return addr;
}

__device__ __forceinline__ void cp_async16(uint32_t dst, const void* src, int src_bytes) {
    asm volatile("cp.async.cg.shared.global [%0], [%1], 16, %2;"
                 :: "r"(dst), "l"(src), "r"(src_bytes));
}
#define CP_ASYNC_COMMIT() asm volatile("cp.async.commit_group;" ::: "memory")
#define CP_ASYNC_WAIT_2() asm volatile("cp.async.wait_group 2;" ::: "memory")

#define LDMATRIX_X4(r0, r1, r2, r3, addr) \
    asm volatile("ldmatrix.sync.aligned.m8n8.x4.shared.b16 {%0,%1,%2,%3}, [%4];" \
                 : "=r"(r0), "=r"(r1), "=r"(r2), "=r"(r3) : "r"(addr))

#define MMA_16816(d, a0, a1, a2, a3, b0, b1) \
    asm volatile("mma.sync.aligned.m16n8k16.row.col.f32.f16.f16.f32 " \
                 "{%0,%1,%2,%3}, {%4,%5,%6,%7}, {%8,%9}, {%0,%1,%2,%3};" \
                 : "+f"((d)[0]), "+f"((d)[1]), "+f"((d)[2]), "+f"((d)[3]) \
                 : "r"(a0), "r"(a1), "r"(a2), "r"(a3), "r"(b0), "r"(b1))

// ---------------------------------------------------------------------------
// 1. Weight convert (fp32 -> fp16)
// ---------------------------------------------------------------------------
__global__ void convert_weights_kernel(const float* __restrict__ wih,
                                       const float* __restrict__ whh) {
    const int n1 = H3 * K1;
    const int n2 = H3 * K2;
    for (int i = blockIdx.x * blockDim.x + threadIdx.x; i < n1 + n2;
         i += gridDim.x * blockDim.x) {
        if (i < n1) g_Wih_h[i] = __float2half_rn(wih[i]);
        else        g_Whh_h[i - n1] = __float2half_rn(whh[i - n1]);
    }
}

__global__ void zero_loss_kernel() { g_loss = 0.0f; }

// ---------------------------------------------------------------------------
// 2. Prep: loss + feats einsum + relu*mask -> g_gruin (fp16)
// ---------------------------------------------------------------------------
__global__ void __launch_bounds__(256) prep_kernel(
    const float* __restrict__ p, const float* __restrict__ X,
    const float* __restrict__ M, const int* __restrict__ iobs,
    const float* __restrict__ wprep, const float* __restrict__ bprep) {
    __shared__ float sw[D_IN * 64];   // [d][f*16+j]
    __shared__ float sb[D_IN * PH];
    __shared__ float sred[256];

    for (int i = threadIdx.x; i < D_IN * 64; i += 256) sw[i] = wprep[i];
    for (int i = threadIdx.x; i < D_IN * PH; i += 256) sb[i] = bprep[i];
    __syncthreads();

    const int d   = threadIdx.x & 63;
    const int sub = threadIdx.x >> 6;   // 0..3
    const int base = blockIdx.x * 32;
    float lacc = 0.0f;

    for (int rr = sub; rr < 32; rr += 4) {
        const int r = base + rr;
        if (r >= NOBS) continue;
        const int i = iobs[r];
        const float mean = p[(size_t)i * 128 + d];
        const float var  = fabsf(p[(size_t)i * 128 + 64 + d]) + 1e-6f;
        const float x    = X[(size_t)r * 64 + d];
        const float m    = M[(size_t)r * 64 + d];
        const float rsv  = rsqrtf(var);
        const float err  = (x - mean) * rsv;
        lacc += 0.5f * (err * err + logf(var)) * m;

        const float* w = sw + d * 64;
        const float* b = sb + d * 16;
        __half2 hv[8];
        #pragma unroll
        for (int j = 0; j < 16; j += 2) {
            float v0 = b[j];
            v0 = fmaf(x, w[j], v0);
            v0 = fmaf(mean, w[16 + j], v0);
            v0 = fmaf(var,  w[32 + j], v0);
            v0 = fmaf(err,  w[48 + j], v0);
            float v1 = b[j + 1];
            v1 = fmaf(x, w[j + 1], v1);
            v1 = fmaf(mean, w[16 + j + 1], v1);
            v1 = fmaf(var,  w[32 + j + 1], v1);
            v1 = fmaf(err,  w[48 + j + 1], v1);
            v0 = fmaxf(v0, 0.0f) * m;
            v1 = fmaxf(v1, 0.0f) * m;
            hv[j >> 1] = __floats2half2_rn(v0, v1);
        }
        uint4* dst = reinterpret_cast<uint4*>(&g_gruin[(size_t)r * K1 + d * 16]);
        dst[0] = *reinterpret_cast<uint4*>(&hv[0]);
        dst[1] = *reinterpret_cast<uint4*>(&hv[4]);
    }

    sred[threadIdx.x] = lacc;
    __syncthreads();
    for (int s = 128; s > 0; s >>= 1) {
        if (threadIdx.x < s) sred[threadIdx.x] += sred[threadIdx.x + s];
        __syncthreads();
    }
    if (threadIdx.x == 0) atomicAdd(&g_loss, sred[0]);
}

// ---------------------------------------------------------------------------
// 3. Gather h[i_obs] -> fp16
// ---------------------------------------------------------------------------
__global__ void gather_h_kernel(const float* __restrict__ h,
                                const int* __restrict__ iobs) {
    const int total = NOBS * (HID / 2);
    int idx = blockIdx.x * blockDim.x + threadIdx.x;
    if (idx >= total) return;
    const int r = idx >> 8;          // HID/2 = 256
    const int c = idx & 255;
    const int i = iobs[r];
    float2 v = *reinterpret_cast<const float2*>(&h[(size_t)i * HID + c * 2]);
    reinterpret_cast<__half2*>(g_hgat)[idx] = __floats2half2_rn(v.x, v.y);
}

// ---------------------------------------------------------------------------
// 4. HMMA GEMM (round-4 roofline version): C[M,1536] = A[M,K] @ B[1536,K]^T
//    At the legacy HMMA rate ceiling (~300 TF/s) — mainloop frozen.
// ---------------------------------------------------------------------------
#define STAGES       4
#define STAGE_BYTES  20480          // A 10240 + B 10240
#define SM_B_OFF     10240

__device__ __forceinline__ void load_stage(uint32_t sm, int stage,
                                           const __half* __restrict__ A,
                                           const __half* __restrict__ B,
                                           int m0, int n0, int K, int kc, int tid) {
    const uint32_t base = sm + stage * STAGE_BYTES;
    #pragma unroll
    for (int it = 0; it < 4; it++) {
        const int c = tid + it * 256;           // 0..1023
        const int cc = c & 511;
        const int row = cc >> 2, ch = cc & 3;   // 128 rows x 4 x 16B
        if (c < 512) {  // A
            const int rg = m0 + row;
            const int rc = rg < NOBS ? rg : (NOBS - 1);
            const void* src = A + (size_t)rc * K + kc * 32 + ch * 8;
            cp_async16(base + row * 80 + ch * 16, src, rg < NOBS ? 16 : 0);
        } else {        // B (always in range)
            const void* src = B + (size_t)(n0 + row) * K + kc * 32 + ch * 8;
            cp_async16(base + SM_B_OFF + row * 80 + ch * 16, src, 16);
        }
    }
}

__global__ void __launch_bounds__(256, 2) gemm_hmma_kernel(
    const __half* __restrict__ A, const __half* __restrict__ B,
    __half* __restrict__ C, int K) {
    extern __shared__ __align__(128) char smem[];   // STAGES * STAGE_BYTES
    const uint32_t sm = smem_to_u32(smem);

    const int tid  = threadIdx.x;
    const int lane = tid & 31;
    const int wid  = tid >> 5;
    const int warp_m = wid & 3;     // 4 m-warps, 32 rows each
    const int warp_n = wid >> 2;    // 2 n-warps, 64 cols each

    const int n0 = blockIdx.x * 128;
    const int m0 = blockIdx.y * 128;
    const int nk = K >> 5;

    const uint32_t lrow = lane & 15;
    const uint32_t lcol = (lane >> 4) << 4;   // 0 or 16 bytes
    const uint32_t a_off = (warp_m * 32 + lrow) * 80 + lcol;
    const uint32_t b_off = SM_B_OFF + (warp_n * 64 + lrow) * 80 + lcol;

    float acc[2][8][4];
    #pragma unroll
    for (int mt = 0; mt < 2; mt++)
        #pragma unroll
        for (int nt = 0; nt < 8; nt++)
            #pragma unroll
            for (int e = 0; e < 4; e++) acc[mt][nt][e] = 0.0f;

    #pragma unroll
    for (int s = 0; s < 3; s++) {
        load_stage(sm, s, A, B, m0, n0, K, s, tid);
        CP_ASYNC_COMMIT();
    }

    for (int kc = 0; kc < nk; kc++) {
        const int buf = kc & 3;
        CP_ASYNC_WAIT_2();
        __syncthreads();

        if (kc + 3 < nk) load_stage(sm, (kc + 3) & 3, A, B, m0, n0, K, kc + 3, tid);
        CP_ASYNC_COMMIT();

        const uint32_t sA = sm + buf * STAGE_BYTES;

        #pragma unroll
        for (int ks = 0; ks < 2; ks++) {
            const uint32_t k0b = ks * 32;
            uint32_t a[2][4];
            LDMATRIX_X4(a[0][0], a[0][1], a[0][2], a[0][3], sA + a_off + k0b);
            LDMATRIX_X4(a[1][0], a[1][1], a[1][2], a[1][3], sA + a_off + 1280 + k0b);
            uint32_t b[8][2];
            #pragma unroll
            for (int nb = 0; nb < 4; nb++) {
                uint32_t r0, r1, r2, r3;
                LDMATRIX_X4(r0, r1, r2, r3, sA + b_off + nb * 1280 + k0b);
                b[2 * nb][0] = r0; b[2 * nb][1] = r2;
                b[2 * nb + 1][0] = r1; b[2 * nb + 1][1] = r3;
            }
            #pragma unroll
            for (int mt = 0; mt < 2; mt++)
                #pragma unroll
                for (int nt = 0; nt < 8; nt++)
                    MMA_16816(acc[mt][nt],
                              a[mt][0], a[mt][1], a[mt][2], a[mt][3],
                              b[nt][0], b[nt][1]);
        }
    }

    #pragma unroll
    for (int mt = 0; mt < 2; mt++) {
        const int r0 = m0 + warp_m * 32 + mt * 16 + (lane >> 2);
        #pragma unroll
        for (int nt = 0; nt < 8; nt++) {
            const int col = n0 + warp_n * 64 + nt * 8 + (lane & 3) * 2;
            if (r0 < NOBS)
                *reinterpret_cast<__half2*>(&C[(size_t)r0 * H3 + col]) =
                    __floats2half2_rn(acc[mt][nt][0], acc[mt][nt][1]);
            if (r0 + 8 < NOBS)
                *reinterpret_cast<__half2*>(&C[(size_t)(r0 + 8) * H3 + col]) =
                    __floats2half2_rn(acc[mt][nt][2], acc[mt][nt][3]);
        }
    }
}

// ---------------------------------------------------------------------------
// 5. Gate combine + scatter (last occurrence of each index wins)
// ---------------------------------------------------------------------------
__global__ void __launch_bounds__(128) combine_kernel(
    const int* __restrict__ iobs, const float* __restrict__ h,
    const float* __restrict__ bih, const float* __restrict__ bhh,
    float* __restrict__ out) {
    const int r = blockIdx.x;
    const int i = iobs[r];
    if (r + 1 < NOBS && iobs[r + 1] == i) return;   // not last occurrence

    const __half2* gi = reinterpret_cast<const __half2*>(&g_gi[(size_t)r * H3]);
    const __half2* gh = reinterpret_cast<const __half2*>(&g_gh[(size_t)r * H3]);
    const float2* b_ih = reinterpret_cast<const float2*>(bih);
    const float2* b_hh = reinterpret_cast<const float2*>(bhh);
    const float2* hrow = reinterpret_cast<const float2*>(&h[(size_t)i * HID]);
    float2* orow = reinterpret_cast<float2*>(&out[(size_t)i * HID]);

    for (int j = threadIdx.x; j < HID / 2; j += 128) {
        const float2 gir = __half22float2(gi[j]);
        const float2 giz = __half22float2(gi[256 + j]);
        const float2 gin = __half22float2(gi[512 + j]);
        const float2 ghr = __half22float2(gh[j]);
        const float2 ghz = __half22float2(gh[256 + j]);
        const float2 ghn = __half22float2(gh[512 + j]);
        const float2 bir = b_ih[j],       bhr = b_hh[j];
        const float2 biz = b_ih[256 + j], bhz = b_hh[256 + j];
        const float2 bin = b_ih[512 + j], bhn = b_hh[512 + j];
        const float2 hp = hrow[j];

        const float rg0 = 1.0f / (1.0f + expf(-(gir.x + bir.x + ghr.x + bhr.x)));
        const float rg1 = 1.0f / (1.0f + expf(-(gir.y + bir.y + ghr.y + bhr.y)));
        const float zg0 = 1.0f / (1.0f + expf(-(giz.x + biz.x + ghz.x + bhz.x)));
        const float zg1 = 1.0f / (1.0f + expf(-(giz.y + biz.y + ghz.y + bhz.y)));
        const float nn0 = tanhf(gin.x + bin.x + rg0 * (ghn.x + bhn.x));
        const float nn1 = tanhf(gin.y + bin.y + rg1 * (ghn.y + bhn.y));
        float2 o;
        o.x = (1.0f - zg0) * nn0 + zg0 * hp.x;
        o.y = (1.0f - zg1) * nn1 + zg1 * hp.y;
        orow[j] = o;
    }
}

// ---------------------------------------------------------------------------
// 6. Loss store
// ---------------------------------------------------------------------------
__global__ void write_loss_kernel(float* __restrict__ out) {
    out[(size_t)N_ROWS * HID] = g_loss;
}

// ---------------------------------------------------------------------------
// Launch — fork/join multi-stream graph:
//   branch s1: memcpy h->out                    (join before combine)
//   branch s2: gather h[i_obs]                  (join before GEMM2)
//   branch s3: zero_loss -> prep                (join before GEMM1)
//   spine  s0: convert -> GEMM1 -> GEMM2 -> combine -> loss
// ---------------------------------------------------------------------------
extern "C" void kernel_launch(void* const* d_in, const int* in_sizes, int n_in,
                              void* d_out, int out_size) {
    const float* h     = (const float*)d_in[0];
    const float* p     = (const float*)d_in[1];
    const float* X     = (const float*)d_in[2];
    const float* M     = (const float*)d_in[3];
    const int*   iobs  = (const int*)  d_in[4];
    const float* wprep = (const float*)d_in[5];
    const float* bprep = (const float*)d_in[6];
    const float* wih   = (const float*)d_in[7];
    const float* whh   = (const float*)d_in[8];
    const float* bih   = (const float*)d_in[9];
    const float* bhh   = (const float*)d_in[10];
    float* out = (float*)d_out;

    static bool init_done = false;
    static cudaStream_t s1, s2, s3;
    static cudaEvent_t ev_fork, ev_cpy, ev_gather, ev_prep;
    if (!init_done) {
        cudaFuncSetAttribute(gemm_hmma_kernel,
                             cudaFuncAttributeMaxDynamicSharedMemorySize,
                             STAGES * STAGE_BYTES);
        cudaStreamCreateWithFlags(&s1, cudaStreamNonBlocking);
        cudaStreamCreateWithFlags(&s2, cudaStreamNonBlocking);
        cudaStreamCreateWithFlags(&s3, cudaStreamNonBlocking);
        cudaEventCreateWithFlags(&ev_fork,   cudaEventDisableTiming);
        cudaEventCreateWithFlags(&ev_cpy,    cudaEventDisableTiming);
        cudaEventCreateWithFlags(&ev_gather, cudaEventDisableTiming);
        cudaEventCreateWithFlags(&ev_prep,   cudaEventDisableTiming);
        init_done = true;
    }

    __half *d_gruin, *d_hgat, *d_gi, *d_gh, *d_wih, *d_whh;
    cudaGetSymbolAddress((void**)&d_gruin, g_gruin);
    cudaGetSymbolAddress((void**)&d_hgat,  g_hgat);
    cudaGetSymbolAddress((void**)&d_gi,    g_gi);
    cudaGetSymbolAddress((void**)&d_gh,    g_gh);
    cudaGetSymbolAddress((void**)&d_wih,   g_Wih_h);
    cudaGetSymbolAddress((void**)&d_whh,   g_Whh_h);

    // fork point on the capture (legacy) stream
    cudaEventRecord(ev_fork, 0);

    // branch s1: big copy out[:N*HID] = h — hidden under the GEMMs
    cudaStreamWaitEvent(s1, ev_fork, 0);
    cudaMemcpyAsync(out, h, (size_t)N_ROWS * HID * sizeof(float),
                    cudaMemcpyDeviceToDevice, s1);
    cudaEventRecord(ev_cpy, s1);

    // branch s2: gather h[i_obs] -> fp16 (feeds GEMM2)
    cudaStreamWaitEvent(s2, ev_fork, 0);
    gather_h_kernel<<<(NOBS * (HID / 2) + 255) / 256, 256, 0, s2>>>(h, iobs);
    cudaEventRecord(ev_gather, s2);

    // branch s3: zero loss, then prep (feeds GEMM1; owns g_loss writes)
    cudaStreamWaitEvent(s3, ev_fork, 0);
    zero_loss_kernel<<<1, 1, 0, s3>>>();
    prep_kernel<<<(NOBS + 31) / 32, 256, 0, s3>>>(p, X, M, iobs, wprep, bprep);
    cudaEventRecord(ev_prep, s3);

    // spine: convert weights (concurrent with branches)
    convert_weights_kernel<<<512, 256>>>(wih, whh);

    // GEMM1 = gru_in @ Wih^T  (needs prep + convert)
    cudaStreamWaitEvent(0, ev_prep, 0);
    gemm_hmma_kernel<<<dim3(12, MTILES), 256, STAGES * STAGE_BYTES>>>(
        d_gruin, d_wih, d_gi, K1);

    // GEMM2 = h_gat @ Whh^T  (needs gather + convert)
    cudaStreamWaitEvent(0, ev_gather, 0);
    gemm_hmma_kernel<<<dim3(12, MTILES), 256, STAGES * STAGE_BYTES>>>(
        d_hgat, d_whh, d_gh, K2);

    // combine: gates + scatter (needs both GEMMs and the copy)
    cudaStreamWaitEvent(0, ev_cpy, 0);
    combine_kernel<<<NOBS, 128>>>(iobs, h, bih, bhh, out);

    // loss
    if (out_size > N_ROWS * HID)
        write_loss_kernel<<<1, 1>>>(out);
}

// round 8
// speedup vs baseline: 1.3058x; 1.1691x over previous
#include <cuda_runtime.h>
#include <cuda_fp16.h>
#include <cstdint>

// ---------------------------------------------------------------------------
// Problem constants
// ---------------------------------------------------------------------------
#define N_ROWS 100000
#define HID    512
#define D_IN   64
#define PH     16
#define NOBS   50000
#define K1     1024      // PH*D
#define K2     512       // HID
#define H3     1536      // 3*HID
#define MTILES ((NOBS + 127) / 128)   // 391
#define SCAN_BLK 512
#define NSB ((NOBS + SCAN_BLK - 1) / SCAN_BLK)   // 98

// ---------------------------------------------------------------------------
// Scratch (__device__ globals — sanctioned scratch path, no runtime allocs)
// ---------------------------------------------------------------------------
__device__ __half g_Wih_h[(size_t)H3 * K1];     //  3 MB
__device__ __half g_Whh_h[(size_t)H3 * K2];     //  1.5 MB
__device__ __half g_gruin[(size_t)NOBS * K1];   // 100 MB (compacted rows)
__device__ __half g_hgat [(size_t)NOBS * K2];   //  50 MB (compacted rows)
__device__ __half g_gi   [(size_t)NOBS * H3];   // 150 MB (compacted rows)
__device__ __half g_gh   [(size_t)NOBS * H3];   // 150 MB (compacted rows)
__device__ float  g_loss;
__device__ int    g_blkcnt[NSB];
__device__ int    g_blkoff[NSB];
__device__ int    g_Mc;                 // number of last-occurrence rows
__device__ int    g_slot[NOBS];         // row -> compact slot
__device__ int    g_cidx[NOBS];         // compact slot -> h index

// ---------------------------------------------------------------------------
// Helpers
// ---------------------------------------------------------------------------
__device__ __forceinline__ uint32_t smem_to_u32(const void* smem_ptr) {
    uint32_t addr;
    asm("{ .reg .u64 tmp; cvta.to.shared.u64 tmp, %1; cvt.u32.u64 %0, tmp; }"
        : "=r"(addr) : "l"(smem_ptr));
    return addr;
}

__device__ __forceinline__ void cp_async16(uint32_t dst, const void* src, int src_bytes) {
    asm volatile("cp.async.cg.shared.global [%0], [%1], 16, %2;"
                 :: "r"(dst), "l"(src), "r"(src_bytes));
}
#define CP_ASYNC_COMMIT() asm volatile("cp.async.commit_group;" ::: "memory")
#define CP_ASYNC_WAIT_2() asm volatile("cp.async.wait_group 2;" ::: "memory")

#define LDMATRIX_X4(r0, r1, r2, r3, addr) \
    asm volatile("ldmatrix.sync.aligned.m8n8.x4.shared.b16 {%0,%1,%2,%3}, [%4];" \
                 : "=r"(r0), "=r"(r1), "=r"(r2), "=r"(r3) : "r"(addr))

#define MMA_16816(d, a0, a1, a2, a3, b0, b1) \
    asm volatile("mma.sync.aligned.m16n8k16.row.col.f32.f16.f16.f32 " \
                 "{%0,%1,%2,%3}, {%4,%5,%6,%7}, {%8,%9}, {%0,%1,%2,%3};" \
                 : "+f"((d)[0]), "+f"((d)[1]), "+f"((d)[2]), "+f"((d)[3]) \
                 : "r"(a0), "r"(a1), "r"(a2), "r"(a3), "r"(b0), "r"(b1))

__device__ __forceinline__ int is_last(const int* iobs, int r) {
    return (r == NOBS - 1) || (iobs[r + 1] != iobs[r]);
}

// ---------------------------------------------------------------------------
// 0. Compaction scan (3 tiny kernels)
// ---------------------------------------------------------------------------
__global__ void __launch_bounds__(SCAN_BLK) scanA_kernel(const int* __restrict__ iobs) {
    __shared__ int sh[SCAN_BLK];
    const int r = blockIdx.x * SCAN_BLK + threadIdx.x;
    sh[threadIdx.x] = (r < NOBS) ? is_last(iobs, r) : 0;
    __syncthreads();
    for (int s = SCAN_BLK / 2; s > 0; s >>= 1) {
        if (threadIdx.x < s) sh[threadIdx.x] += sh[threadIdx.x + s];
        __syncthreads();
    }
    if (threadIdx.x == 0) g_blkcnt[blockIdx.x] = sh[0];
}

__global__ void scanB_kernel() {
    if (threadIdx.x == 0) {
        int acc = 0;
        for (int b = 0; b < NSB; b++) { g_blkoff[b] = acc; acc += g_blkcnt[b]; }
        g_Mc = acc;
    }
}

__global__ void __launch_bounds__(SCAN_BLK) scanC_kernel(const int* __restrict__ iobs) {
    __shared__ int sh[SCAN_BLK];
    const int r = blockIdx.x * SCAN_BLK + threadIdx.x;
    const int last = (r < NOBS) ? is_last(iobs, r) : 0;
    sh[threadIdx.x] = last;
    __syncthreads();
    // Hillis-Steele inclusive scan
    for (int off = 1; off < SCAN_BLK; off <<= 1) {
        int v = (threadIdx.x >= off) ? sh[threadIdx.x - off] : 0;
        __syncthreads();
        sh[threadIdx.x] += v;
        __syncthreads();
    }
    if (r < NOBS) {
        const int slot = g_blkoff[blockIdx.x] + sh[threadIdx.x] - last;  // exclusive
        g_slot[r] = slot;
        if (last) g_cidx[slot] = iobs[r];
    }
}

// ---------------------------------------------------------------------------
// 1. Weight convert (fp32 -> fp16) + copy kernel + loss zero
// ---------------------------------------------------------------------------
__global__ void convert_weights_kernel(const float* __restrict__ wih,
                                       const float* __restrict__ whh) {
    const int n1 = H3 * K1;
    const int n2 = H3 * K2;
    for (int i = blockIdx.x * blockDim.x + threadIdx.x; i < n1 + n2;
         i += gridDim.x * blockDim.x) {
        if (i < n1) g_Wih_h[i] = __float2half_rn(wih[i]);
        else        g_Whh_h[i - n1] = __float2half_rn(whh[i - n1]);
    }
}

__global__ void zero_loss_kernel() { g_loss = 0.0f; }

__global__ void __launch_bounds__(256) copy_h_kernel(const float* __restrict__ h,
                                                     float* __restrict__ out) {
    const size_t n = (size_t)N_ROWS * HID / 4;
    const float4* src = reinterpret_cast<const float4*>(h);
    float4* dst = reinterpret_cast<float4*>(out);
    for (size_t i = blockIdx.x * blockDim.x + threadIdx.x; i < n;
         i += (size_t)gridDim.x * blockDim.x)
        dst[i] = src[i];
}

// ---------------------------------------------------------------------------
// 2. Prep: loss (all rows) + feats einsum (last rows, compacted) -> g_gruin
// ---------------------------------------------------------------------------
__global__ void __launch_bounds__(256) prep_kernel(
    const float* __restrict__ p, const float* __restrict__ X,
    const float* __restrict__ M, const int* __restrict__ iobs,
    const float* __restrict__ wprep, const float* __restrict__ bprep) {
    __shared__ float sw[D_IN * 64];   // [d][f*16+j]
    __shared__ float sb[D_IN * PH];
    __shared__ float sred[256];

    for (int i = threadIdx.x; i < D_IN * 64; i += 256) sw[i] = wprep[i];
    for (int i = threadIdx.x; i < D_IN * PH; i += 256) sb[i] = bprep[i];
    __syncthreads();

    const int d   = threadIdx.x & 63;
    const int sub = threadIdx.x >> 6;   // 0..3
    const int base = blockIdx.x * 32;
    float lacc = 0.0f;

    for (int rr = sub; rr < 32; rr += 4) {
        const int r = base + rr;
        if (r >= NOBS) continue;
        const int i = iobs[r];
        const float mean = p[(size_t)i * 128 + d];
        const float var  = fabsf(p[(size_t)i * 128 + 64 + d]) + 1e-6f;
        const float x    = X[(size_t)r * 64 + d];
        const float m    = M[(size_t)r * 64 + d];
        const float rsv  = rsqrtf(var);
        const float err  = (x - mean) * rsv;
        lacc += 0.5f * (err * err + logf(var)) * m;

        if (!is_last(iobs, r)) continue;   // gru_in only needed for survivors

        const float* w = sw + d * 64;
        const float* b = sb + d * 16;
        __half2 hv[8];
        #pragma unroll
        for (int j = 0; j < 16; j += 2) {
            float v0 = b[j];
            v0 = fmaf(x, w[j], v0);
            v0 = fmaf(mean, w[16 + j], v0);
            v0 = fmaf(var,  w[32 + j], v0);
            v0 = fmaf(err,  w[48 + j], v0);
            float v1 = b[j + 1];
            v1 = fmaf(x, w[j + 1], v1);
            v1 = fmaf(mean, w[16 + j + 1], v1);
            v1 = fmaf(var,  w[32 + j + 1], v1);
            v1 = fmaf(err,  w[48 + j + 1], v1);
            v0 = fmaxf(v0, 0.0f) * m;
            v1 = fmaxf(v1, 0.0f) * m;
            hv[j >> 1] = __floats2half2_rn(v0, v1);
        }
        const int slot = g_slot[r];
        uint4* dst = reinterpret_cast<uint4*>(&g_gruin[(size_t)slot * K1 + d * 16]);
        dst[0] = *reinterpret_cast<uint4*>(&hv[0]);
        dst[1] = *reinterpret_cast<uint4*>(&hv[4]);
    }

    sred[threadIdx.x] = lacc;
    __syncthreads();
    for (int s = 128; s > 0; s >>= 1) {
        if (threadIdx.x < s) sred[threadIdx.x] += sred[threadIdx.x + s];
        __syncthreads();
    }
    if (threadIdx.x == 0) atomicAdd(&g_loss, sred[0]);
}

// ---------------------------------------------------------------------------
// 3. Gather h[cidx[s]] -> fp16 (compacted)
// ---------------------------------------------------------------------------
__global__ void gather_h_kernel(const float* __restrict__ h) {
    const int idx = blockIdx.x * blockDim.x + threadIdx.x;
    const int s = idx >> 8;          // HID/2 = 256
    if (s >= g_Mc) return;
    const int c = idx & 255;
    const int i = g_cidx[s];
    float2 v = *reinterpret_cast<const float2*>(&h[(size_t)i * HID + c * 2]);
    reinterpret_cast<__half2*>(g_hgat)[idx] = __floats2half2_rn(v.x, v.y);
}

// ---------------------------------------------------------------------------
// 4. HMMA GEMM (roofline mainloop, dynamic M = g_Mc):
//    C[Mc,1536] = A[Mc,K] @ B[1536,K]^T
// ---------------------------------------------------------------------------
#define STAGES       4
#define STAGE_BYTES  20480          // A 10240 + B 10240
#define SM_B_OFF     10240

__device__ __forceinline__ void load_stage(uint32_t sm, int stage,
                                           const __half* __restrict__ A,
                                           const __half* __restrict__ B,
                                           int m0, int n0, int K, int kc,
                                           int tid, int Mrows) {
    const uint32_t base = sm + stage * STAGE_BYTES;
    #pragma unroll
    for (int it = 0; it < 4; it++) {
        const int c = tid + it * 256;           // 0..1023
        const int cc = c & 511;
        const int row = cc >> 2, ch = cc & 3;   // 128 rows x 4 x 16B
        if (c < 512) {  // A
            const int rg = m0 + row;
            const int rc = rg < Mrows ? rg : (Mrows - 1);
            const void* src = A + (size_t)rc * K + kc * 32 + ch * 8;
            cp_async16(base + row * 80 + ch * 16, src, rg < Mrows ? 16 : 0);
        } else {        // B (always in range)
            const void* src = B + (size_t)(n0 + row) * K + kc * 32 + ch * 8;
            cp_async16(base + SM_B_OFF + row * 80 + ch * 16, src, 16);
        }
    }
}

__global__ void __launch_bounds__(256, 2) gemm_hmma_kernel(
    const __half* __restrict__ A, const __half* __restrict__ B,
    __half* __restrict__ C, int K) {
    const int Mrows = g_Mc;
    const int m0 = blockIdx.y * 128;
    if (m0 >= Mrows) return;                      // surplus m-tiles exit

    extern __shared__ __align__(128) char smem[];   // STAGES * STAGE_BYTES
    const uint32_t sm = smem_to_u32(smem);

    const int tid  = threadIdx.x;
    const int lane = tid & 31;
    const int wid  = tid >> 5;
    const int warp_m = wid & 3;     // 4 m-warps, 32 rows each
    const int warp_n = wid >> 2;    // 2 n-warps, 64 cols each

    const int n0 = blockIdx.x * 128;
    const int nk = K >> 5;

    const uint32_t lrow = lane & 15;
    const uint32_t lcol = (lane >> 4) << 4;   // 0 or 16 bytes
    const uint32_t a_off = (warp_m * 32 + lrow) * 80 + lcol;
    const uint32_t b_off = SM_B_OFF + (warp_n * 64 + lrow) * 80 + lcol;

    float acc[2][8][4];
    #pragma unroll
    for (int mt = 0; mt < 2; mt++)
        #pragma unroll
        for (int nt = 0; nt < 8; nt++)
            #pragma unroll
            for (int e = 0; e < 4; e++) acc[mt][nt][e] = 0.0f;

    #pragma unroll
    for (int s = 0; s < 3; s++) {
        load_stage(sm, s, A, B, m0, n0, K, s, tid, Mrows);
        CP_ASYNC_COMMIT();
    }

    for (int kc = 0; kc < nk; kc++) {
        const int buf = kc & 3;
        CP_ASYNC_WAIT_2();
        __syncthreads();

        if (kc + 3 < nk)
            load_stage(sm, (kc + 3) & 3, A, B, m0, n0, K, kc + 3, tid, Mrows);
        CP_ASYNC_COMMIT();

        const uint32_t sA = sm + buf * STAGE_BYTES;

        #pragma unroll
        for (int ks = 0; ks < 2; ks++) {
            const uint32_t k0b = ks * 32;
            uint32_t a[2][4];
            LDMATRIX_X4(a[0][0], a[0][1], a[0][2], a[0][3], sA + a_off + k0b);
            LDMATRIX_X4(a[1][0], a[1][1], a[1][2], a[1][3], sA + a_off + 1280 + k0b);
            uint32_t b[8][2];
            #pragma unroll
            for (int nb = 0; nb < 4; nb++) {
                uint32_t r0, r1, r2, r3;
                LDMATRIX_X4(r0, r1, r2, r3, sA + b_off + nb * 1280 + k0b);
                b[2 * nb][0] = r0; b[2 * nb][1] = r2;
                b[2 * nb + 1][0] = r1; b[2 * nb + 1][1] = r3;
            }
            #pragma unroll
            for (int mt = 0; mt < 2; mt++)
                #pragma unroll
                for (int nt = 0; nt < 8; nt++)
                    MMA_16816(acc[mt][nt],
                              a[mt][0], a[mt][1], a[mt][2], a[mt][3],
                              b[nt][0], b[nt][1]);
        }
    }

    #pragma unroll
    for (int mt = 0; mt < 2; mt++) {
        const int r0 = m0 + warp_m * 32 + mt * 16 + (lane >> 2);
        #pragma unroll
        for (int nt = 0; nt < 8; nt++) {
            const int col = n0 + warp_n * 64 + nt * 8 + (lane & 3) * 2;
            if (r0 < Mrows)
                *reinterpret_cast<__half2*>(&C[(size_t)r0 * H3 + col]) =
                    __floats2half2_rn(acc[mt][nt][0], acc[mt][nt][1]);
            if (r0 + 8 < Mrows)
                *reinterpret_cast<__half2*>(&C[(size_t)(r0 + 8) * H3 + col]) =
                    __floats2half2_rn(acc[mt][nt][2], acc[mt][nt][3]);
        }
    }
}

// ---------------------------------------------------------------------------
// 5. Gate combine + scatter (one block per compact slot — no duplicates)
// ---------------------------------------------------------------------------
__global__ void __launch_bounds__(128) combine_kernel(
    const float* __restrict__ h,
    const float* __restrict__ bih, const float* __restrict__ bhh,
    float* __restrict__ out) {
    const int s = blockIdx.x;
    if (s >= g_Mc) return;
    const int i = g_cidx[s];

    const __half2* gi = reinterpret_cast<const __half2*>(&g_gi[(size_t)s * H3]);
    const __half2* gh = reinterpret_cast<const __half2*>(&g_gh[(size_t)s * H3]);
    const float2* b_ih = reinterpret_cast<const float2*>(bih);
    const float2* b_hh = reinterpret_cast<const float2*>(bhh);
    const float2* hrow = reinterpret_cast<const float2*>(&h[(size_t)i * HID]);
    float2* orow = reinterpret_cast<float2*>(&out[(size_t)i * HID]);

    for (int j = threadIdx.x; j < HID / 2; j += 128) {
        const float2 gir = __half22float2(gi[j]);
        const float2 giz = __half22float2(gi[256 + j]);
        const float2 gin = __half22float2(gi[512 + j]);
        const float2 ghr = __half22float2(gh[j]);
        const float2 ghz = __half22float2(gh[256 + j]);
        const float2 ghn = __half22float2(gh[512 + j]);
        const float2 bir = b_ih[j],       bhr = b_hh[j];
        const float2 biz = b_ih[256 + j], bhz = b_hh[256 + j];
        const float2 bin = b_ih[512 + j], bhn = b_hh[512 + j];
        const float2 hp = hrow[j];

        const float rg0 = 1.0f / (1.0f + expf(-(gir.x + bir.x + ghr.x + bhr.x)));
        const float rg1 = 1.0f / (1.0f + expf(-(gir.y + bir.y + ghr.y + bhr.y)));
        const float zg0 = 1.0f / (1.0f + expf(-(giz.x + biz.x + ghz.x + bhz.x)));
        const float zg1 = 1.0f / (1.0f + expf(-(giz.y + biz.y + ghz.y + bhz.y)));
        const float nn0 = tanhf(gin.x + bin.x + rg0 * (ghn.x + bhn.x));
        const float nn1 = tanhf(gin.y + bin.y + rg1 * (ghn.y + bhn.y));
        float2 o;
        o.x = (1.0f - zg0) * nn0 + zg0 * hp.x;
        o.y = (1.0f - zg1) * nn1 + zg1 * hp.y;
        orow[j] = o;
    }
}

// ---------------------------------------------------------------------------
// 6. Loss store
// ---------------------------------------------------------------------------
__global__ void write_loss_kernel(float* __restrict__ out) {
    out[(size_t)N_ROWS * HID] = g_loss;
}

// ---------------------------------------------------------------------------
// Launch — fork/join graph with compaction:
//   s1: copy h->out (kernel; co-resident with GEMMs)     join before combine
//   s3: scanA->scanB->scanC -> zero_loss -> prep         join before GEMM1
//   s2: (after scanC) gather                             join before GEMM2
//   s0: convert -> GEMM1 -> GEMM2 -> combine -> loss
// ---------------------------------------------------------------------------
extern "C" void kernel_launch(void* const* d_in, const int* in_sizes, int n_in,
                              void* d_out, int out_size) {
    const float* h     = (const float*)d_in[0];
    const float* p     = (const float*)d_in[1];
    const float* X     = (const float*)d_in[2];
    const float* M     = (const float*)d_in[3];
    const int*   iobs  = (const int*)  d_in[4];
    const float* wprep = (const float*)d_in[5];
    const float* bprep = (const float*)d_in[6];
    const float* wih   = (const float*)d_in[7];
    const float* whh   = (const float*)d_in[8];
    const float* bih   = (const float*)d_in[9];
    const float* bhh   = (const float*)d_in[10];
    float* out = (float*)d_out;

    static bool init_done = false;
    static cudaStream_t s1, s2, s3;
    static cudaEvent_t ev_fork, ev_cpy, ev_scan, ev_gather, ev_prep;
    if (!init_done) {
        cudaFuncSetAttribute(gemm_hmma_kernel,
                             cudaFuncAttributeMaxDynamicSharedMemorySize,
                             STAGES * STAGE_BYTES);
        cudaStreamCreateWithFlags(&s1, cudaStreamNonBlocking);
        cudaStreamCreateWithFlags(&s2, cudaStreamNonBlocking);
        cudaStreamCreateWithFlags(&s3, cudaStreamNonBlocking);
        cudaEventCreateWithFlags(&ev_fork,   cudaEventDisableTiming);
        cudaEventCreateWithFlags(&ev_cpy,    cudaEventDisableTiming);
        cudaEventCreateWithFlags(&ev_scan,   cudaEventDisableTiming);
        cudaEventCreateWithFlags(&ev_gather, cudaEventDisableTiming);
        cudaEventCreateWithFlags(&ev_prep,   cudaEventDisableTiming);
        init_done = true;
    }

    __half *d_gruin, *d_hgat, *d_gi, *d_gh, *d_wih, *d_whh;
    cudaGetSymbolAddress((void**)&d_gruin, g_gruin);
    cudaGetSymbolAddress((void**)&d_hgat,  g_hgat);
    cudaGetSymbolAddress((void**)&d_gi,    g_gi);
    cudaGetSymbolAddress((void**)&d_gh,    g_gh);
    cudaGetSymbolAddress((void**)&d_wih,   g_Wih_h);
    cudaGetSymbolAddress((void**)&d_whh,   g_Whh_h);

    // fork point on the capture (legacy) stream
    cudaEventRecord(ev_fork, 0);

    // branch s1: copy out[:N*HID] = h via SM kernel (co-resident with GEMMs)
    cudaStreamWaitEvent(s1, ev_fork, 0);
    copy_h_kernel<<<2048, 256, 0, s1>>>(h, out);
    cudaEventRecord(ev_cpy, s1);

    // branch s3: compaction scan, then loss zero + prep
    cudaStreamWaitEvent(s3, ev_fork, 0);
    scanA_kernel<<<NSB, SCAN_BLK, 0, s3>>>(iobs);
    scanB_kernel<<<1, 32, 0, s3>>>();
    scanC_kernel<<<NSB, SCAN_BLK, 0, s3>>>(iobs);
    cudaEventRecord(ev_scan, s3);
    zero_loss_kernel<<<1, 1, 0, s3>>>();
    prep_kernel<<<(NOBS + 31) / 32, 256, 0, s3>>>(p, X, M, iobs, wprep, bprep);
    cudaEventRecord(ev_prep, s3);

    // branch s2: gather (needs scanC's cidx/Mc)
    cudaStreamWaitEvent(s2, ev_scan, 0);
    gather_h_kernel<<<(NOBS * (HID / 2) + 255) / 256, 256, 0, s2>>>(h);
    cudaEventRecord(ev_gather, s2);

    // spine: convert weights (concurrent with branches)
    convert_weights_kernel<<<512, 256>>>(wih, whh);

    // GEMM1 = gru_in @ Wih^T  (needs prep + convert)
    cudaStreamWaitEvent(0, ev_prep, 0);
    gemm_hmma_kernel<<<dim3(12, MTILES), 256, STAGES * STAGE_BYTES>>>(
        d_gruin, d_wih, d_gi, K1);

    // GEMM2 = h_gat @ Whh^T  (needs gather + convert)
    cudaStreamWaitEvent(0, ev_gather, 0);
    gemm_hmma_kernel<<<dim3(12, MTILES), 256, STAGES * STAGE_BYTES>>>(
        d_hgat, d_whh, d_gh, K2);

    // combine: gates + scatter (needs both GEMMs and the copy)
    cudaStreamWaitEvent(0, ev_cpy, 0);
    combine_kernel<<<NOBS, 128>>>(h, bih, bhh, out);

    // loss
    if (out_size > N_ROWS * HID)
        write_loss_kernel<<<1, 1>>>(out);
}

// round 9
// speedup vs baseline: 1.3131x; 1.0056x over previous
#include <cuda_runtime.h>
#include <cuda_fp16.h>
#include <cstdint>

// ---------------------------------------------------------------------------
// Problem constants
// ---------------------------------------------------------------------------
#define N_ROWS 100000
#define HID    512
#define D_IN   64
#define PH     16
#define NOBS   50000
#define K1     1024      // PH*D
#define K2     512       // HID
#define H3     1536      // 3*HID
#define MTILES ((NOBS + 127) / 128)   // 391
#define SCAN_BLK 512
#define NSB ((NOBS + SCAN_BLK - 1) / SCAN_BLK)   // 98

// ---------------------------------------------------------------------------
// Scratch (__device__ globals — sanctioned scratch path, no runtime allocs)
// ---------------------------------------------------------------------------
__device__ __half g_Wih_h[(size_t)H3 * K1];     //  3 MB
__device__ __half g_Whh_h[(size_t)H3 * K2];     //  1.5 MB
__device__ __half g_gruin[(size_t)NOBS * K1];   // 100 MB (compacted rows)
__device__ __half g_hgat [(size_t)NOBS * K2];   //  50 MB (compacted rows)
__device__ __half g_gi   [(size_t)NOBS * H3];   // 150 MB (compacted rows)
__device__ __half g_gh   [(size_t)NOBS * H3];   // 150 MB (compacted rows)
__device__ float  g_loss;
__device__ int    g_blkcnt[NSB];
__device__ int    g_blkoff[NSB];
__device__ int    g_Mc;                 // number of last-occurrence rows
__device__ int    g_slot[NOBS];         // obs row -> compact slot
__device__ int    g_cidx[NOBS];         // compact slot -> h index
__device__ int    g_rowslot[N_ROWS];    // h row -> compact slot (or -1)

// ---------------------------------------------------------------------------
// Helpers
// ---------------------------------------------------------------------------
__device__ __forceinline__ uint32_t smem_to_u32(const void* smem_ptr) {
    uint32_t addr;
    asm("{ .reg .u64 tmp; cvta.to.shared.u64 tmp, %1; cvt.u32.u64 %0, tmp; }"
        : "=r"(addr) : "l"(smem_ptr));
    return addr;
}

__device__ __forceinline__ void cp_async16(uint32_t dst, const void* src, int src_bytes) {
    asm volatile("cp.async.cg.shared.global [%0], [%1], 16, %2;"
                 :: "r"(dst), "l"(src), "r"(src_bytes));
}
#define CP_ASYNC_COMMIT() asm volatile("cp.async.commit_group;" ::: "memory")
#define CP_ASYNC_WAIT_2() asm volatile("cp.async.wait_group 2;" ::: "memory")

#define LDMATRIX_X4(r0, r1, r2, r3, addr) \
    asm volatile("ldmatrix.sync.aligned.m8n8.x4.shared.b16 {%0,%1,%2,%3}, [%4];" \
                 : "=r"(r0), "=r"(r1), "=r"(r2), "=r"(r3) : "r"(addr))

#define MMA_16816(d, a0, a1, a2, a3, b0, b1) \
    asm volatile("mma.sync.aligned.m16n8k16.row.col.f32.f16.f16.f32 " \
                 "{%0,%1,%2,%3}, {%4,%5,%6,%7}, {%8,%9}, {%0,%1,%2,%3};" \
                 : "+f"((d)[0]), "+f"((d)[1]), "+f"((d)[2]), "+f"((d)[3]) \
                 : "r"(a0), "r"(a1), "r"(a2), "r"(a3), "r"(b0), "r"(b1))

__device__ __forceinline__ int is_last(const int* iobs, int r) {
    return (r == NOBS - 1) || (iobs[r + 1] != iobs[r]);
}

// ---------------------------------------------------------------------------
// 0a. Init: zero loss + rowslot = -1
// ---------------------------------------------------------------------------
__global__ void __launch_bounds__(256) init_kernel() {
    if (blockIdx.x == 0 && threadIdx.x == 0) g_loss = 0.0f;
    for (int i = blockIdx.x * blockDim.x + threadIdx.x; i < N_ROWS;
         i += gridDim.x * blockDim.x)
        g_rowslot[i] = -1;
}

// ---------------------------------------------------------------------------
// 0b. Compaction scan (3 tiny kernels)
// ---------------------------------------------------------------------------
__global__ void __launch_bounds__(SCAN_BLK) scanA_kernel(const int* __restrict__ iobs) {
    __shared__ int sh[SCAN_BLK];
    const int r = blockIdx.x * SCAN_BLK + threadIdx.x;
    sh[threadIdx.x] = (r < NOBS) ? is_last(iobs, r) : 0;
    __syncthreads();
    for (int s = SCAN_BLK / 2; s > 0; s >>= 1) {
        if (threadIdx.x < s) sh[threadIdx.x] += sh[threadIdx.x + s];
        __syncthreads();
    }
    if (threadIdx.x == 0) g_blkcnt[blockIdx.x] = sh[0];
}

__global__ void scanB_kernel() {
    if (threadIdx.x == 0) {
        int acc = 0;
        for (int b = 0; b < NSB; b++) { g_blkoff[b] = acc; acc += g_blkcnt[b]; }
        g_Mc = acc;
    }
}

__global__ void __launch_bounds__(SCAN_BLK) scanC_kernel(const int* __restrict__ iobs) {
    __shared__ int sh[SCAN_BLK];
    const int r = blockIdx.x * SCAN_BLK + threadIdx.x;
    const int last = (r < NOBS) ? is_last(iobs, r) : 0;
    sh[threadIdx.x] = last;
    __syncthreads();
    // Hillis-Steele inclusive scan
    for (int off = 1; off < SCAN_BLK; off <<= 1) {
        int v = (threadIdx.x >= off) ? sh[threadIdx.x - off] : 0;
        __syncthreads();
        sh[threadIdx.x] += v;
        __syncthreads();
    }
    if (r < NOBS) {
        const int slot = g_blkoff[blockIdx.x] + sh[threadIdx.x] - last;  // exclusive
        g_slot[r] = slot;
        if (last) {
            const int i = iobs[r];
            g_cidx[slot] = i;
            g_rowslot[i] = slot;
        }
    }
}

// ---------------------------------------------------------------------------
// 1. Weight convert (fp32 -> fp16), vectorized
// ---------------------------------------------------------------------------
__global__ void __launch_bounds__(256) convert_weights_kernel(
    const float* __restrict__ wih, const float* __restrict__ whh) {
    const int q1 = H3 * K1 / 4;
    const int q2 = H3 * K2 / 4;
    for (int i = blockIdx.x * blockDim.x + threadIdx.x; i < q1 + q2;
         i += gridDim.x * blockDim.x) {
        float4 v;
        __half2* dst;
        if (i < q1) {
            v = reinterpret_cast<const float4*>(wih)[i];
            dst = reinterpret_cast<__half2*>(&g_Wih_h[(size_t)i * 4]);
        } else {
            v = reinterpret_cast<const float4*>(whh)[i - q1];
            dst = reinterpret_cast<__half2*>(&g_Whh_h[(size_t)(i - q1) * 4]);
        }
        dst[0] = __floats2half2_rn(v.x, v.y);
        dst[1] = __floats2half2_rn(v.z, v.w);
    }
}

// ---------------------------------------------------------------------------
// 2. Prep: loss (all rows) + feats einsum (last rows, compacted) -> g_gruin
// ---------------------------------------------------------------------------
__global__ void __launch_bounds__(256) prep_kernel(
    const float* __restrict__ p, const float* __restrict__ X,
    const float* __restrict__ M, const int* __restrict__ iobs,
    const float* __restrict__ wprep, const float* __restrict__ bprep) {
    __shared__ float sw[D_IN * 64];   // [d][f*16+j]
    __shared__ float sb[D_IN * PH];
    __shared__ float sred[256];

    for (int i = threadIdx.x; i < D_IN * 64; i += 256) sw[i] = wprep[i];
    for (int i = threadIdx.x; i < D_IN * PH; i += 256) sb[i] = bprep[i];
    __syncthreads();

    const int d   = threadIdx.x & 63;
    const int sub = threadIdx.x >> 6;   // 0..3
    const int base = blockIdx.x * 32;
    float lacc = 0.0f;

    for (int rr = sub; rr < 32; rr += 4) {
        const int r = base + rr;
        if (r >= NOBS) continue;
        const int i = iobs[r];
        const float mean = p[(size_t)i * 128 + d];
        const float var  = fabsf(p[(size_t)i * 128 + 64 + d]) + 1e-6f;
        const float x    = X[(size_t)r * 64 + d];
        const float m    = M[(size_t)r * 64 + d];
        const float rsv  = rsqrtf(var);
        const float err  = (x - mean) * rsv;
        lacc += 0.5f * (err * err + logf(var)) * m;

        if (!is_last(iobs, r)) continue;   // gru_in only needed for survivors

        const float* w = sw + d * 64;
        const float* b = sb + d * 16;
        __half2 hv[8];
        #pragma unroll
        for (int j = 0; j < 16; j += 2) {
            float v0 = b[j];
            v0 = fmaf(x, w[j], v0);
            v0 = fmaf(mean, w[16 + j], v0);
            v0 = fmaf(var,  w[32 + j], v0);
            v0 = fmaf(err,  w[48 + j], v0);
            float v1 = b[j + 1];
            v1 = fmaf(x, w[j + 1], v1);
            v1 = fmaf(mean, w[16 + j + 1], v1);
            v1 = fmaf(var,  w[32 + j + 1], v1);
            v1 = fmaf(err,  w[48 + j + 1], v1);
            v0 = fmaxf(v0, 0.0f) * m;
            v1 = fmaxf(v1, 0.0f) * m;
            hv[j >> 1] = __floats2half2_rn(v0, v1);
        }
        const int slot = g_slot[r];
        uint4* dst = reinterpret_cast<uint4*>(&g_gruin[(size_t)slot * K1 + d * 16]);
        dst[0] = *reinterpret_cast<uint4*>(&hv[0]);
        dst[1] = *reinterpret_cast<uint4*>(&hv[4]);
    }

    sred[threadIdx.x] = lacc;
    __syncthreads();
    for (int s = 128; s > 0; s >>= 1) {
        if (threadIdx.x < s) sred[threadIdx.x] += sred[threadIdx.x + s];
        __syncthreads();
    }
    if (threadIdx.x == 0) atomicAdd(&g_loss, sred[0]);
}

// ---------------------------------------------------------------------------
// 3. Gather h[cidx[s]] -> fp16 (compacted)
// ---------------------------------------------------------------------------
__global__ void gather_h_kernel(const float* __restrict__ h) {
    const int idx = blockIdx.x * blockDim.x + threadIdx.x;
    const int s = idx >> 8;          // HID/2 = 256
    if (s >= g_Mc) return;
    const int c = idx & 255;
    const int i = g_cidx[s];
    float2 v = *reinterpret_cast<const float2*>(&h[(size_t)i * HID + c * 2]);
    reinterpret_cast<__half2*>(g_hgat)[idx] = __floats2half2_rn(v.x, v.y);
}

// ---------------------------------------------------------------------------
// 4. HMMA GEMM (roofline mainloop, dynamic M = g_Mc):
//    C[Mc,1536] = A[Mc,K] @ B[1536,K]^T
// ---------------------------------------------------------------------------
#define STAGES       4
#define STAGE_BYTES  20480          // A 10240 + B 10240
#define SM_B_OFF     10240

__device__ __forceinline__ void load_stage(uint32_t sm, int stage,
                                           const __half* __restrict__ A,
                                           const __half* __restrict__ B,
                                           int m0, int n0, int K, int kc,
                                           int tid, int Mrows) {
    const uint32_t base = sm + stage * STAGE_BYTES;
    #pragma unroll
    for (int it = 0; it < 4; it++) {
        const int c = tid + it * 256;           // 0..1023
        const int cc = c & 511;
        const int row = cc >> 2, ch = cc & 3;   // 128 rows x 4 x 16B
        if (c < 512) {  // A
            const int rg = m0 + row;
            const int rc = rg < Mrows ? rg : (Mrows - 1);
            const void* src = A + (size_t)rc * K + kc * 32 + ch * 8;
            cp_async16(base + row * 80 + ch * 16, src, rg < Mrows ? 16 : 0);
        } else {        // B (always in range)
            const void* src = B + (size_t)(n0 + row) * K + kc * 32 + ch * 8;
            cp_async16(base + SM_B_OFF + row * 80 + ch * 16, src, 16);
        }
    }
}

__global__ void __launch_bounds__(256, 2) gemm_hmma_kernel(
    const __half* __restrict__ A, const __half* __restrict__ B,
    __half* __restrict__ C, int K) {
    const int Mrows = g_Mc;
    const int m0 = blockIdx.y * 128;
    if (m0 >= Mrows) return;                      // surplus m-tiles exit

    extern __shared__ __align__(128) char smem[];   // STAGES * STAGE_BYTES
    const uint32_t sm = smem_to_u32(smem);

    const int tid  = threadIdx.x;
    const int lane = tid & 31;
    const int wid  = tid >> 5;
    const int warp_m = wid & 3;     // 4 m-warps, 32 rows each
    const int warp_n = wid >> 2;    // 2 n-warps, 64 cols each

    const int n0 = blockIdx.x * 128;
    const int nk = K >> 5;

    const uint32_t lrow = lane & 15;
    const uint32_t lcol = (lane >> 4) << 4;   // 0 or 16 bytes
    const uint32_t a_off = (warp_m * 32 + lrow) * 80 + lcol;
    const uint32_t b_off = SM_B_OFF + (warp_n * 64 + lrow) * 80 + lcol;

    float acc[2][8][4];
    #pragma unroll
    for (int mt = 0; mt < 2; mt++)
        #pragma unroll
        for (int nt = 0; nt < 8; nt++)
            #pragma unroll
            for (int e = 0; e < 4; e++) acc[mt][nt][e] = 0.0f;

    #pragma unroll
    for (int s = 0; s < 3; s++) {
        load_stage(sm, s, A, B, m0, n0, K, s, tid, Mrows);
        CP_ASYNC_COMMIT();
    }

    for (int kc = 0; kc < nk; kc++) {
        const int buf = kc & 3;
        CP_ASYNC_WAIT_2();
        __syncthreads();

        if (kc + 3 < nk)
            load_stage(sm, (kc + 3) & 3, A, B, m0, n0, K, kc + 3, tid, Mrows);
        CP_ASYNC_COMMIT();

        const uint32_t sA = sm + buf * STAGE_BYTES;

        #pragma unroll
        for (int ks = 0; ks < 2; ks++) {
            const uint32_t k0b = ks * 32;
            uint32_t a[2][4];
            LDMATRIX_X4(a[0][0], a[0][1], a[0][2], a[0][3], sA + a_off + k0b);
            LDMATRIX_X4(a[1][0], a[1][1], a[1][2], a[1][3], sA + a_off + 1280 + k0b);
            uint32_t b[8][2];
            #pragma unroll
            for (int nb = 0; nb < 4; nb++) {
                uint32_t r0, r1, r2, r3;
                LDMATRIX_X4(r0, r1, r2, r3, sA + b_off + nb * 1280 + k0b);
                b[2 * nb][0] = r0; b[2 * nb][1] = r2;
                b[2 * nb + 1][0] = r1; b[2 * nb + 1][1] = r3;
            }
            #pragma unroll
            for (int mt = 0; mt < 2; mt++)
                #pragma unroll
                for (int nt = 0; nt < 8; nt++)
                    MMA_16816(acc[mt][nt],
                              a[mt][0], a[mt][1], a[mt][2], a[mt][3],
                              b[nt][0], b[nt][1]);
        }
    }

    #pragma unroll
    for (int mt = 0; mt < 2; mt++) {
        const int r0 = m0 + warp_m * 32 + mt * 16 + (lane >> 2);
        #pragma unroll
        for (int nt = 0; nt < 8; nt++) {
            const int col = n0 + warp_n * 64 + nt * 8 + (lane & 3) * 2;
            if (r0 < Mrows)
                *reinterpret_cast<__half2*>(&C[(size_t)r0 * H3 + col]) =
                    __floats2half2_rn(acc[mt][nt][0], acc[mt][nt][1]);
            if (r0 + 8 < Mrows)
                *reinterpret_cast<__half2*>(&C[(size_t)(r0 + 8) * H3 + col]) =
                    __floats2half2_rn(acc[mt][nt][2], acc[mt][nt][3]);
        }
    }
}

// ---------------------------------------------------------------------------
// 5. Unified output: per h-row, either copy h or gate-combine (one pass)
//    256 threads = 2 rows per block (128 threads per row).
// ---------------------------------------------------------------------------
__global__ void __launch_bounds__(256) out_kernel(
    const float* __restrict__ h,
    const float* __restrict__ bih, const float* __restrict__ bhh,
    float* __restrict__ out) {
    const int row = blockIdx.x * 2 + (threadIdx.x >> 7);
    if (row >= N_ROWS) return;
    const int t = threadIdx.x & 127;            // float4 lane: 128*4 = 512 ✓
    const int s = g_rowslot[row];

    const float4* hrow4 = reinterpret_cast<const float4*>(&h[(size_t)row * HID]);
    float4* orow4 = reinterpret_cast<float4*>(&out[(size_t)row * HID]);

    if (s < 0) {                                 // not updated: plain copy
        orow4[t] = hrow4[t];
        return;
    }

    const __half2* gi = reinterpret_cast<const __half2*>(&g_gi[(size_t)s * H3]);
    const __half2* gh = reinterpret_cast<const __half2*>(&g_gh[(size_t)s * H3]);
    const float4* b_ih4 = reinterpret_cast<const float4*>(bih);
    const float4* b_hh4 = reinterpret_cast<const float4*>(bhh);

    // half2 indices for this thread's 4 elements
    const int j0 = 2 * t, j1 = 2 * t + 1;
    const float2 ir0 = __half22float2(gi[j0]),        ir1 = __half22float2(gi[j1]);
    const float2 iz0 = __half22float2(gi[256 + j0]),  iz1 = __half22float2(gi[256 + j1]);
    const float2 in0 = __half22float2(gi[512 + j0]),  in1 = __half22float2(gi[512 + j1]);
    const float2 hr0 = __half22float2(gh[j0]),        hr1 = __half22float2(gh[j1]);
    const float2 hz0 = __half22float2(gh[256 + j0]),  hz1 = __half22float2(gh[256 + j1]);
    const float2 hn0 = __half22float2(gh[512 + j0]),  hn1 = __half22float2(gh[512 + j1]);
    const float4 bir = b_ih4[t],       bhr = b_hh4[t];
    const float4 biz = b_ih4[128 + t], bhz = b_hh4[128 + t];
    const float4 bin = b_ih4[256 + t], bhn = b_hh4[256 + t];
    const float4 hp = hrow4[t];

    float rr[4], zz[4], nn[4];
    const float irs[4] = {ir0.x + bir.x + hr0.x + bhr.x, ir0.y + bir.y + hr0.y + bhr.y,
                          ir1.x + bir.z + hr1.x + bhr.z, ir1.y + bir.w + hr1.y + bhr.w};
    const float izs[4] = {iz0.x + biz.x + hz0.x + bhz.x, iz0.y + biz.y + hz0.y + bhz.y,
                          iz1.x + biz.z + hz1.x + bhz.z, iz1.y + biz.w + hz1.y + bhz.w};
    const float ins[4] = {in0.x + bin.x, in0.y + bin.y, in1.x + bin.z, in1.y + bin.w};
    const float hns[4] = {hn0.x + bhn.x, hn0.y + bhn.y, hn1.x + bhn.z, hn1.y + bhn.w};
    #pragma unroll
    for (int e = 0; e < 4; e++) {
        rr[e] = 1.0f / (1.0f + expf(-irs[e]));
        zz[e] = 1.0f / (1.0f + expf(-izs[e]));
        nn[e] = tanhf(ins[e] + rr[e] * hns[e]);
    }
    float4 o;
    o.x = (1.0f - zz[0]) * nn[0] + zz[0] * hp.x;
    o.y = (1.0f - zz[1]) * nn[1] + zz[1] * hp.y;
    o.z = (1.0f - zz[2]) * nn[2] + zz[2] * hp.z;
    o.w = (1.0f - zz[3]) * nn[3] + zz[3] * hp.w;
    orow4[t] = o;
}

// ---------------------------------------------------------------------------
// 6. Loss store
// ---------------------------------------------------------------------------
__global__ void write_loss_kernel(float* __restrict__ out) {
    out[(size_t)N_ROWS * HID] = g_loss;
}

// ---------------------------------------------------------------------------
// Launch — single stream (graph executes serially anyway; minimize nodes+work)
// ---------------------------------------------------------------------------
extern "C" void kernel_launch(void* const* d_in, const int* in_sizes, int n_in,
                              void* d_out, int out_size) {
    const float* h     = (const float*)d_in[0];
    const float* p     = (const float*)d_in[1];
    const float* X     = (const float*)d_in[2];
    const float* M     = (const float*)d_in[3];
    const int*   iobs  = (const int*)  d_in[4];
    const float* wprep = (const float*)d_in[5];
    const float* bprep = (const float*)d_in[6];
    const float* wih   = (const float*)d_in[7];
    const float* whh   = (const float*)d_in[8];
    const float* bih   = (const float*)d_in[9];
    const float* bhh   = (const float*)d_in[10];
    float* out = (float*)d_out;

    static bool init_done = false;
    if (!init_done) {
        cudaFuncSetAttribute(gemm_hmma_kernel,
                             cudaFuncAttributeMaxDynamicSharedMemorySize,
                             STAGES * STAGE_BYTES);
        init_done = true;
    }

    __half *d_gruin, *d_hgat, *d_gi, *d_gh, *d_wih, *d_whh;
    cudaGetSymbolAddress((void**)&d_gruin, g_gruin);
    cudaGetSymbolAddress((void**)&d_hgat,  g_hgat);
    cudaGetSymbolAddress((void**)&d_gi,    g_gi);
    cudaGetSymbolAddress((void**)&d_gh,    g_gh);
    cudaGetSymbolAddress((void**)&d_wih,   g_Wih_h);
    cudaGetSymbolAddress((void**)&d_whh,   g_Whh_h);

    // 1. init (loss = 0, rowslot = -1)
    init_kernel<<<256, 256>>>();

    // 2-4. compaction scan
    scanA_kernel<<<NSB, SCAN_BLK>>>(iobs);
    scanB_kernel<<<1, 32>>>();
    scanC_kernel<<<NSB, SCAN_BLK>>>(iobs);

    // 5. convert weights to fp16
    convert_weights_kernel<<<512, 256>>>(wih, whh);

    // 6. prep: loss + gru_in (compacted)
    prep_kernel<<<(NOBS + 31) / 32, 256>>>(p, X, M, iobs, wprep, bprep);

    // 7. gather h[cidx] -> fp16 (compacted)
    gather_h_kernel<<<(NOBS * (HID / 2) + 255) / 256, 256>>>(h);

    // 8. gi = gru_in @ Wih^T   (Mc x 1536 x 1024)
    gemm_hmma_kernel<<<dim3(12, MTILES), 256, STAGES * STAGE_BYTES>>>(
        d_gruin, d_wih, d_gi, K1);

    // 9. gh = h_gat @ Whh^T    (Mc x 1536 x 512)
    gemm_hmma_kernel<<<dim3(12, MTILES), 256, STAGES * STAGE_BYTES>>>(
        d_hgat, d_whh, d_gh, K2);

    // 10. unified output: copy or gate-combine per row
    out_kernel<<<(N_ROWS + 1) / 2, 256>>>(h, bih, bhh, out);

    // 11. loss
    if (out_size > N_ROWS * HID)
        write_loss_kernel<<<1, 1>>>(out);
}